// round 10
// baseline (speedup 1.0000x reference)
#include <cuda_runtime.h>
#include <cuda_bf16.h>

#define FULL_MASK 0xFFFFFFFFu
#define HC 3                 // chunks per half-warp-team: S = 192 = 2 halves * 3 * 32
#define RAYS_PER_BLOCK 4     // 256 threads = 8 warps = 4 rays * 2 warps

// TWO warps per ray (each owns 96 samples = 3 chunks of 32). All global loads
// front-batched per warp (15 LDGs back-to-back -> high MLP). Each warp runs 3
// interleaved 32-wide prefix-product scans; the only cross-warp dependency is
// one carry product exchanged through shared memory.
__global__ void __launch_bounds__(256, 5) nerf_render_kernel(
    const float* __restrict__ rgb,     // [N, S, 3]
    const float* __restrict__ sigma,   // [N, S]
    const float* __restrict__ z_vals,  // [N, S]
    const float* __restrict__ rays_d,  // [N, 3]
    float* __restrict__ out,           // flattened 7-tuple
    int N)
{
    const int S = 192;
    const int lane = threadIdx.x & 31;
    const int wid  = threadIdx.x >> 5;
    const int rayLocal = wid >> 1;           // 0..3
    const int half     = wid & 1;            // 0 = samples [0,96), 1 = [96,192)
    const int ray = blockIdx.x * RAYS_PER_BLOCK + rayLocal;
    if (ray >= N) return;

    __shared__ float s_carry[RAYS_PER_BLOCK];
    __shared__ float s_part[RAYS_PER_BLOCK][2][6];

    const size_t NS = (size_t)N * (size_t)S;
    float* out_rgb   = out;
    float* out_depth = out + (size_t)3 * N;
    float* out_acc   = out + (size_t)4 * N;
    float* out_w     = out + (size_t)5 * N;
    float* out_disp  = out + (size_t)5 * N + NS;
    float* out_trans = out + (size_t)6 * N + NS;
    float* out_alpha = out + (size_t)6 * N + 2 * NS;

    const int soff = half * 96;                       // sample offset of this warp
    const float* zr  = z_vals + (size_t)ray * S + soff;
    const float* sr  = sigma  + (size_t)ray * S + soff;
    const float* crf = rgb    + (size_t)ray * S * 3 + (size_t)soff * 3;
    float* wr = out_w     + (size_t)ray * S + soff;
    float* tr = out_trans + (size_t)ray * S + soff;
    float* ar = out_alpha + (size_t)ray * S + soff;

    // ---------------- Phase A: batch ALL global loads (15 LDGs) -------------
    float z[HC], sg[HC];
    #pragma unroll
    for (int c = 0; c < HC; c++) {
        z[c]  = __ldcs(zr + c * 32 + lane);
        sg[c] = __ldcs(sr + c * 32 + lane);
    }
    float v[HC][3];   // flat coalesced rgb: v[c][j] = flat float (96c + lane + 32j)
    #pragma unroll
    for (int c = 0; c < HC; c++) {
        #pragma unroll
        for (int j = 0; j < 3; j++)
            v[c][j] = __ldcs(crf + c * 96 + lane + 32 * j);
    }
    const float dx = rays_d[ray * 3 + 0];
    const float dy = rays_d[ray * 3 + 1];
    const float dz = rays_d[ray * 3 + 2];
    const float norm = sqrtf(dx * dx + dy * dy + dz * dz);

    // Gather pattern for flat rgb layout (within this warp's 96 samples):
    // flat f = 96c + lane + 32j -> chunk-local source lane (lane+32j)/3, channel f%3
    const int s0 = lane / 3,          ch0 = lane % 3;
    const int s1 = (lane + 32) / 3,   ch1 = (lane + 32) % 3;
    const int s2 = (lane + 64) / 3,   ch2 = (lane + 64) % 3;

    // ---------------- Phase B: alpha / survival ----------------
    float alpha[HC], incl[HC];
    #pragma unroll
    for (int c = 0; c < HC; c++) {
        float znext = __shfl_down_sync(FULL_MASK, z[c], 1);
        if (c < HC - 1) {
            float nxt0 = __shfl_sync(FULL_MASK, z[c + 1], 0);
            if (lane == 31) znext = nxt0;
        }
        float dist_raw;
        if (c == HC - 1 && lane == 31) {
            // boundary: half 0 needs z[96] (lives in warp 1's line -> cache hit);
            // half 1 is the global last sample -> 1e10
            dist_raw = (half == 0) ? (__ldg(zr + 96) - z[c]) : 1e10f;
        } else {
            dist_raw = znext - z[c];
        }
        float x = fmaxf(sg[c], 0.0f) * (dist_raw * norm);
        alpha[c] = 1.0f - __expf(-x);
        incl[c]  = 1.0f - alpha[c];
    }

    // ---------------- Phase C: 3 independent inclusive scans (ILP) ----------
    #pragma unroll
    for (int off = 1; off < 32; off <<= 1) {
        #pragma unroll
        for (int c = 0; c < HC; c++) {
            float t = __shfl_up_sync(FULL_MASK, incl[c], off);
            if (lane >= off) incl[c] *= t;
        }
    }
    float excl[HC], tot[HC];
    #pragma unroll
    for (int c = 0; c < HC; c++) {
        tot[c]  = __shfl_sync(FULL_MASK, incl[c], 31);
        excl[c] = __shfl_up_sync(FULL_MASK, incl[c], 1);
        if (lane == 0) excl[c] = 1.0f;
    }

    // ---------------- Phase D: cross-warp carry exchange ----------
    if (half == 0 && lane == 0)
        s_carry[rayLocal] = tot[0] * tot[1] * tot[2];
    __syncthreads();
    float carry = (half == 1) ? s_carry[rayLocal] : 1.0f;

    float trans[HC];
    #pragma unroll
    for (int c = 0; c < HC; c++) {
        trans[c] = carry * excl[c];
        carry *= tot[c];
    }

    // ---------------- Phase E: weights, stores, accumulations --------------
    float accJ0 = 0.f, accJ1 = 0.f, accJ2 = 0.f;
    float accD = 0.f, accA = 0.f;

    #pragma unroll
    for (int c = 0; c < HC; c++) {
        const float w = alpha[c] * trans[c];

        __stcs(wr + c * 32 + lane, w);
        __stcs(tr + c * 32 + lane, trans[c]);
        __stcs(ar + c * 32 + lane, alpha[c]);

        accD += w * z[c];
        accA += w;

        accJ0 += __shfl_sync(FULL_MASK, w, s0) * v[c][0];
        accJ1 += __shfl_sync(FULL_MASK, w, s1) * v[c][1];
        accJ2 += __shfl_sync(FULL_MASK, w, s2) * v[c][2];
    }

    float accR = (ch0 == 0 ? accJ0 : 0.f) + (ch1 == 0 ? accJ1 : 0.f) + (ch2 == 0 ? accJ2 : 0.f);
    float accG = (ch0 == 1 ? accJ0 : 0.f) + (ch1 == 1 ? accJ1 : 0.f) + (ch2 == 1 ? accJ2 : 0.f);
    float accB = (ch0 == 2 ? accJ0 : 0.f) + (ch1 == 2 ? accJ1 : 0.f) + (ch2 == 2 ? accJ2 : 0.f);

    // warp reduce the 5 scalars
    #pragma unroll
    for (int off = 16; off > 0; off >>= 1) {
        accR += __shfl_down_sync(FULL_MASK, accR, off);
        accG += __shfl_down_sync(FULL_MASK, accG, off);
        accB += __shfl_down_sync(FULL_MASK, accB, off);
        accD += __shfl_down_sync(FULL_MASK, accD, off);
        accA += __shfl_down_sync(FULL_MASK, accA, off);
    }

    if (lane == 0) {
        s_part[rayLocal][half][0] = accR;
        s_part[rayLocal][half][1] = accG;
        s_part[rayLocal][half][2] = accB;
        s_part[rayLocal][half][3] = accD;
        s_part[rayLocal][half][4] = accA;
    }
    __syncthreads();

    if (half == 0 && lane == 0) {
        const float R = s_part[rayLocal][0][0] + s_part[rayLocal][1][0];
        const float G = s_part[rayLocal][0][1] + s_part[rayLocal][1][1];
        const float B = s_part[rayLocal][0][2] + s_part[rayLocal][1][2];
        const float D = s_part[rayLocal][0][3] + s_part[rayLocal][1][3];
        const float A = s_part[rayLocal][0][4] + s_part[rayLocal][1][4];
        out_rgb[ray * 3 + 0] = R;
        out_rgb[ray * 3 + 1] = G;
        out_rgb[ray * 3 + 2] = B;
        out_depth[ray] = D;
        out_acc[ray]   = A;
        out_disp[ray]  = 1.0f / fmaxf(1e-10f, D / A);
    }
}

extern "C" void kernel_launch(void* const* d_in, const int* in_sizes, int n_in,
                              void* d_out, int out_size) {
    const float* rgb    = (const float*)d_in[0];
    const float* sigma  = (const float*)d_in[1];
    const float* z_vals = (const float*)d_in[2];
    const float* rays_d = (const float*)d_in[3];
    float* out = (float*)d_out;

    const int N = in_sizes[3] / 3;          // 65536

    const int threads = 256;                       // 8 warps = 4 rays/block
    const int blocks = (N + RAYS_PER_BLOCK - 1) / RAYS_PER_BLOCK;  // 16384
    nerf_render_kernel<<<blocks, threads>>>(rgb, sigma, z_vals, rays_d, out, N);
}

// round 12
// speedup vs baseline: 1.6437x; 1.6437x over previous
#include <cuda_runtime.h>
#include <cuda_bf16.h>

#define FULL_MASK 0xFFFFFFFFu
#define NCHUNK 3           // S = 192 = 3 chunks * 64 samples (2 per lane, float2)

// One warp per ray; each lane owns 2 consecutive samples per chunk (float2).
// All loads front-batched (15 LDG.64 -> high MLP). Prefix product runs over
// per-lane pair products (5 shfl rounds per chunk, 3 chunks interleaved).
// rgb weights are lane-local -> no gather shuffles at all.
__global__ void __launch_bounds__(256) nerf_render_kernel(
    const float* __restrict__ rgb,     // [N, S, 3]
    const float* __restrict__ sigma,   // [N, S]
    const float* __restrict__ z_vals,  // [N, S]
    const float* __restrict__ rays_d,  // [N, 3]
    float* __restrict__ out,           // flattened 7-tuple
    int N)
{
    const int S = 192;
    const int warp_id = (int)((blockIdx.x * blockDim.x + threadIdx.x) >> 5);
    const int lane    = threadIdx.x & 31;
    if (warp_id >= N) return;
    const int ray = warp_id;

    const size_t NS = (size_t)N * (size_t)S;
    float* out_rgb   = out;
    float* out_depth = out + (size_t)3 * N;
    float* out_acc   = out + (size_t)4 * N;
    float* out_w     = out + (size_t)5 * N;
    float* out_disp  = out + (size_t)5 * N + NS;
    float* out_trans = out + (size_t)6 * N + NS;
    float* out_alpha = out + (size_t)6 * N + 2 * NS;

    const float2* zr2  = (const float2*)(z_vals + (size_t)ray * S);
    const float2* sr2  = (const float2*)(sigma  + (size_t)ray * S);
    const float2* cr2  = (const float2*)(rgb    + (size_t)ray * S * 3);
    float2* wr2 = (float2*)(out_w     + (size_t)ray * S);
    float2* tr2 = (float2*)(out_trans + (size_t)ray * S);
    float2* ar2 = (float2*)(out_alpha + (size_t)ray * S);

    // ---------------- Phase A: batch ALL global loads (15 LDG.64) -----------
    float2 z[NCHUNK], sg[NCHUNK];
    #pragma unroll
    for (int c = 0; c < NCHUNK; c++) {
        z[c]  = __ldcs(zr2 + c * 32 + lane);   // samples 64c+2l, +1
        sg[c] = __ldcs(sr2 + c * 32 + lane);
    }
    // rgb: lane owns floats [192c + 6l .. 6l+5] = (r0,g0)(b0,r1)(g1,b1)
    float2 v[NCHUNK][3];
    #pragma unroll
    for (int c = 0; c < NCHUNK; c++) {
        #pragma unroll
        for (int k = 0; k < 3; k++)
            v[c][k] = __ldcs(cr2 + c * 96 + 3 * lane + k);
    }
    const float dx = rays_d[ray * 3 + 0];
    const float dy = rays_d[ray * 3 + 1];
    const float dz = rays_d[ray * 3 + 2];
    const float norm = sqrtf(dx * dx + dy * dy + dz * dz);

    // ---------------- Phase B: alpha / survival per pair --------------------
    float2 alpha[NCHUNK], t[NCHUNK];
    #pragma unroll
    for (int c = 0; c < NCHUNK; c++) {
        // dist for elem 0 is register-local; elem 1 needs next lane's z.x
        float znext = __shfl_down_sync(FULL_MASK, z[c].x, 1);
        if (c < NCHUNK - 1) {
            float nxt0 = __shfl_sync(FULL_MASK, z[c + 1].x, 0);
            if (lane == 31) znext = nxt0;
        }
        const float dist0 = z[c].y - z[c].x;
        const float dist1 = (c == NCHUNK - 1 && lane == 31) ? 1e10f
                                                            : (znext - z[c].y);
        const float x0 = fmaxf(sg[c].x, 0.0f) * (dist0 * norm);
        const float x1 = fmaxf(sg[c].y, 0.0f) * (dist1 * norm);
        const float e0 = __expf(-x0);
        const float e1 = __expf(-x1);
        alpha[c].x = 1.0f - e0;  t[c].x = e0;   // survival = exp(-x)
        alpha[c].y = 1.0f - e1;  t[c].y = e1;
    }

    // ---------------- Phase C: scan of pair products (3 chains, ILP) --------
    float p[NCHUNK];
    #pragma unroll
    for (int c = 0; c < NCHUNK; c++) p[c] = t[c].x * t[c].y;

    #pragma unroll
    for (int off = 1; off < 32; off <<= 1) {
        #pragma unroll
        for (int c = 0; c < NCHUNK; c++) {
            float q = __shfl_up_sync(FULL_MASK, p[c], off);
            if (lane >= off) p[c] *= q;
        }
    }
    float excl[NCHUNK], tot[NCHUNK];
    #pragma unroll
    for (int c = 0; c < NCHUNK; c++) {
        tot[c]  = __shfl_sync(FULL_MASK, p[c], 31);
        excl[c] = __shfl_up_sync(FULL_MASK, p[c], 1);
        if (lane == 0) excl[c] = 1.0f;
    }

    // ---------------- Phase D: carry chain + expand to per-sample trans -----
    float2 trans[NCHUNK];
    {
        float carry = 1.0f;
        #pragma unroll
        for (int c = 0; c < NCHUNK; c++) {
            trans[c].x = carry * excl[c];
            trans[c].y = trans[c].x * t[c].x;
            carry *= tot[c];
        }
    }

    // ---------------- Phase E: weights, stores, lane-local accumulation -----
    float accR = 0.f, accG = 0.f, accB = 0.f, accD = 0.f, accA = 0.f;

    #pragma unroll
    for (int c = 0; c < NCHUNK; c++) {
        float2 w;
        w.x = alpha[c].x * trans[c].x;
        w.y = alpha[c].y * trans[c].y;

        __stcs(wr2 + c * 32 + lane, w);
        __stcs(tr2 + c * 32 + lane, trans[c]);
        __stcs(ar2 + c * 32 + lane, alpha[c]);

        accD += w.x * z[c].x + w.y * z[c].y;
        accA += w.x + w.y;

        // lane-local rgb: (r0,g0)(b0,r1)(g1,b1) — no shuffles
        accR += w.x * v[c][0].x + w.y * v[c][1].y;
        accG += w.x * v[c][0].y + w.y * v[c][2].x;
        accB += w.x * v[c][1].x + w.y * v[c][2].y;
    }

    // warp reduce the 5 scalars
    #pragma unroll
    for (int off = 16; off > 0; off >>= 1) {
        accR += __shfl_down_sync(FULL_MASK, accR, off);
        accG += __shfl_down_sync(FULL_MASK, accG, off);
        accB += __shfl_down_sync(FULL_MASK, accB, off);
        accD += __shfl_down_sync(FULL_MASK, accD, off);
        accA += __shfl_down_sync(FULL_MASK, accA, off);
    }

    if (lane == 0) {
        out_rgb[ray * 3 + 0] = accR;
        out_rgb[ray * 3 + 1] = accG;
        out_rgb[ray * 3 + 2] = accB;
        out_depth[ray] = accD;
        out_acc[ray]   = accA;
        out_disp[ray]  = 1.0f / fmaxf(1e-10f, accD / accA);
    }
}

extern "C" void kernel_launch(void* const* d_in, const int* in_sizes, int n_in,
                              void* d_out, int out_size) {
    const float* rgb    = (const float*)d_in[0];
    const float* sigma  = (const float*)d_in[1];
    const float* z_vals = (const float*)d_in[2];
    const float* rays_d = (const float*)d_in[3];
    float* out = (float*)d_out;

    const int N = in_sizes[3] / 3;          // 65536

    const int threads = 256;                // 8 warps = 8 rays / block
    const int blocks = (N * 32) / threads;  // 8192
    nerf_render_kernel<<<blocks, threads>>>(rgb, sigma, z_vals, rays_d, out, N);
}